// round 1
// baseline (speedup 1.0000x reference)
#include <cuda_runtime.h>
#include <math.h>

#define B    8
#define CIN  512
#define COUT 512
#define H    64
#define W    64
#define KDIM 3
#define KAREA 9
#define RED  (CIN*KAREA)   // 4608 reduction length

// Scratch (static device globals — no allocation allowed)
__device__ float g_S[B*CIN];          // style modulation s[b][i]
__device__ float g_D[B*COUT];         // scale * demod[b][o]
__device__ float g_wT[RED*COUT];      // transposed weight: [i*9+k][o]

// ---------------------------------------------------------------------------
// K1: s[b][i] = dot(style[b], mod_w[i])
// ---------------------------------------------------------------------------
__global__ void k_style(const float* __restrict__ style,
                        const float* __restrict__ mw) {
    __shared__ float st[CIN];
    int b = blockIdx.x;
    st[threadIdx.x] = style[b*CIN + threadIdx.x];
    __syncthreads();
    int i = threadIdx.x;
    const float* row = mw + (size_t)i*CIN;
    float acc = 0.f;
#pragma unroll 8
    for (int j = 0; j < CIN; j++) acc += row[j]*st[j];
    g_S[b*CIN + i] = acc;
}

// ---------------------------------------------------------------------------
// K2: transpose weight [O][RED] -> g_wT[RED][O] (coalesced via 32x32 smem tile)
// ---------------------------------------------------------------------------
__global__ void k_wt(const float* __restrict__ w) {
    __shared__ float t[32][33];
    int r0 = blockIdx.x*32;   // reduction index (i*9+k)
    int o0 = blockIdx.y*32;   // output channel
    int tx = threadIdx.x, ty = threadIdx.y;   // block (32,8)
#pragma unroll
    for (int i = 0; i < 32; i += 8)
        t[ty+i][tx] = w[(size_t)(o0+ty+i)*RED + r0 + tx];
    __syncthreads();
#pragma unroll
    for (int i = 0; i < 32; i += 8)
        g_wT[(size_t)(r0+ty+i)*COUT + o0 + tx] = t[tx][ty+i];
}

// ---------------------------------------------------------------------------
// K3: demod[b][o] = rsqrt(scale^2 * sum_{i,k}(w*s)^2 + 1e-8); store scale*demod
//     one warp per (b,o)
// ---------------------------------------------------------------------------
__global__ void k_demod(const float* __restrict__ w) {
    int gw   = blockIdx.x*8 + (threadIdx.x >> 5);   // 0..B*COUT-1
    int lane = threadIdx.x & 31;
    int b = gw / COUT, o = gw % COUT;
    const float* wrow = w + (size_t)o*RED;
    const float* srow = g_S + b*CIN;
    float sum = 0.f;
    for (int idx = lane; idx < RED; idx += 32) {
        float m = wrow[idx] * srow[idx/9];
        sum += m*m;
    }
#pragma unroll
    for (int off = 16; off; off >>= 1)
        sum += __shfl_xor_sync(0xffffffffu, sum, off);
    if (lane == 0) {
        const float scale  = rsqrtf((float)RED);       // 1/sqrt(4608)
        const float scale2 = 1.0f/(float)RED;
        g_D[gw] = scale * rsqrtf(scale2*sum + 1e-8f);
    }
}

// ---------------------------------------------------------------------------
// K4: main conv. Block tile: 64 couts x (8 rows x 32 cols) pixels.
//     Thread (tm in [0,8), tn in [0,32)) owns 8 couts x 8 pixel-rows.
//     cin chunk = 8. x-tile modulated by s at smem load.
// ---------------------------------------------------------------------------
#define TM 64
#define TH 8
#define TW 32
#define CC 8

__global__ void __launch_bounds__(256, 2)
k_conv(const float* __restrict__ x, float* __restrict__ out) {
    __shared__ __align__(16) float xs[CC][TH+2][TW+2];
    __shared__ __align__(16) float ws[CC*KAREA][TM];

    const int b   = blockIdx.z;
    const int co0 = blockIdx.y * TM;
    const int y0  = (blockIdx.x >> 1) * TH;
    const int x0  = (blockIdx.x & 1)  * TW;
    const int tid = threadIdx.x;
    const int tn  = tid & 31;
    const int tm  = tid >> 5;

    float acc[8][8];
#pragma unroll
    for (int mi = 0; mi < 8; mi++)
#pragma unroll
        for (int py = 0; py < 8; py++) acc[mi][py] = 0.f;

    const float* sb = g_S + b*CIN;
    const float* xb = x + (size_t)b*CIN*H*W;

    for (int cc = 0; cc < CIN; cc += CC) {
        __syncthreads();   // protect smem reuse across iterations

        // --- load x tile (with halo), modulated by s[b][ci] ---
        for (int idx = tid; idx < CC*(TH+2)*(TW+2); idx += 256) {
            int ci  = idx / ((TH+2)*(TW+2));
            int rem = idx % ((TH+2)*(TW+2));
            int yy  = rem / (TW+2);
            int xx  = rem % (TW+2);
            int gy  = y0 + yy - 1;
            int gx  = x0 + xx - 1;
            float v = 0.f;
            if (gy >= 0 && gy < H && gx >= 0 && gx < W)
                v = xb[((size_t)(cc+ci)*H + gy)*W + gx] * sb[cc+ci];
            xs[ci][yy][xx] = v;
        }

        // --- load weight tile: rows (ci,k) in chunk, 64 contiguous couts ---
        {
            const float4* wt4 = (const float4*)(g_wT + (size_t)cc*KAREA*COUT + co0);
            float4* ws4 = (float4*)ws;
            for (int idx = tid; idx < CC*KAREA*(TM/4); idx += 256) {
                int r = idx >> 4;      // 0..71
                int c = idx & 15;      // float4 within 64-cout row
                ws4[r*(TM/4) + c] = wt4[(size_t)r*(COUT/4) + c];
            }
        }
        __syncthreads();

        // --- compute ---
        for (int ci = 0; ci < CC; ci++) {
#pragma unroll
            for (int ky = 0; ky < 3; ky++) {
#pragma unroll
                for (int kx = 0; kx < 3; kx++) {
                    const int r = ci*KAREA + ky*3 + kx;
                    float4 wa = *(const float4*)&ws[r][tm*8];
                    float4 wb = *(const float4*)&ws[r][tm*8+4];
                    float w8[8] = {wa.x, wa.y, wa.z, wa.w,
                                   wb.x, wb.y, wb.z, wb.w};
                    float xv[8];
#pragma unroll
                    for (int py = 0; py < 8; py++)
                        xv[py] = xs[ci][py+ky][tn+kx];
#pragma unroll
                    for (int mi = 0; mi < 8; mi++)
#pragma unroll
                        for (int py = 0; py < 8; py++)
                            acc[mi][py] = fmaf(w8[mi], xv[py], acc[mi][py]);
                }
            }
        }
    }

    // --- epilogue: apply scale*demod, store ---
    float dv[8];
#pragma unroll
    for (int mi = 0; mi < 8; mi++)
        dv[mi] = g_D[b*COUT + co0 + tm*8 + mi];
#pragma unroll
    for (int mi = 0; mi < 8; mi++) {
        int o = co0 + tm*8 + mi;
        float* op = out + (((size_t)b*COUT + o)*H + y0)*W + x0 + tn;
#pragma unroll
        for (int py = 0; py < 8; py++)
            op[(size_t)py*W] = acc[mi][py] * dv[mi];
    }
}

// ---------------------------------------------------------------------------
extern "C" void kernel_launch(void* const* d_in, const int* in_sizes, int n_in,
                              void* d_out, int out_size) {
    // Identify inputs by element count (all distinct) — robust to ordering.
    const float *x = nullptr, *style = nullptr, *weight = nullptr, *mod_w = nullptr;
    for (int i = 0; i < n_in; i++) {
        switch (in_sizes[i]) {
            case B*CIN*H*W:        x      = (const float*)d_in[i]; break; // 16777216
            case B*CIN:            style  = (const float*)d_in[i]; break; // 4096
            case COUT*CIN*KAREA:   weight = (const float*)d_in[i]; break; // 2359296
            case CIN*CIN:          mod_w  = (const float*)d_in[i]; break; // 262144
        }
    }
    float* out = (float*)d_out;

    k_style<<<B, CIN>>>(style, mod_w);

    dim3 gt(RED/32, COUT/32);
    k_wt<<<gt, dim3(32,8)>>>(weight);

    k_demod<<<(B*COUT)/8, 256>>>(weight);

    dim3 gc((H/TH)*(W/TW), COUT/TM, B);
    k_conv<<<gc, 256>>>(x, out);
}

// round 2
// speedup vs baseline: 1.0007x; 1.0007x over previous
#include <cuda_runtime.h>
#include <math.h>

#define B    8
#define CIN  512
#define COUT 512
#define H    64
#define W    64
#define KDIM 3
#define KAREA 9
#define RED  (CIN*KAREA)   // 4608 reduction length

// Scratch (static device globals — no allocation allowed)
__device__ float g_S[B*CIN];          // style modulation s[b][i]
__device__ float g_D[B*COUT];         // scale * demod[b][o]
__device__ float g_wT[RED*COUT];      // transposed weight: [i*9+k][o]

// ---------------------------------------------------------------------------
// K1: s[b][i] = dot(style[b], mod_w[i])
// ---------------------------------------------------------------------------
__global__ void k_style(const float* __restrict__ style,
                        const float* __restrict__ mw) {
    __shared__ float st[CIN];
    int b = blockIdx.x;
    st[threadIdx.x] = style[b*CIN + threadIdx.x];
    __syncthreads();
    int i = threadIdx.x;
    const float* row = mw + (size_t)i*CIN;
    float acc = 0.f;
#pragma unroll 8
    for (int j = 0; j < CIN; j++) acc += row[j]*st[j];
    g_S[b*CIN + i] = acc;
}

// ---------------------------------------------------------------------------
// K2: transpose weight [O][RED] -> g_wT[RED][O] (coalesced via 32x32 smem tile)
// ---------------------------------------------------------------------------
__global__ void k_wt(const float* __restrict__ w) {
    __shared__ float t[32][33];
    int r0 = blockIdx.x*32;   // reduction index (i*9+k)
    int o0 = blockIdx.y*32;   // output channel
    int tx = threadIdx.x, ty = threadIdx.y;   // block (32,8)
#pragma unroll
    for (int i = 0; i < 32; i += 8)
        t[ty+i][tx] = w[(size_t)(o0+ty+i)*RED + r0 + tx];
    __syncthreads();
#pragma unroll
    for (int i = 0; i < 32; i += 8)
        g_wT[(size_t)(r0+ty+i)*COUT + o0 + tx] = t[tx][ty+i];
}

// ---------------------------------------------------------------------------
// K3: demod[b][o] = rsqrt(scale^2 * sum_{i,k}(w*s)^2 + 1e-8); store scale*demod
//     one warp per (b,o)
// ---------------------------------------------------------------------------
__global__ void k_demod(const float* __restrict__ w) {
    int gw   = blockIdx.x*8 + (threadIdx.x >> 5);   // 0..B*COUT-1
    int lane = threadIdx.x & 31;
    int b = gw / COUT, o = gw % COUT;
    const float* wrow = w + (size_t)o*RED;
    const float* srow = g_S + b*CIN;
    float sum = 0.f;
    for (int idx = lane; idx < RED; idx += 32) {
        float m = wrow[idx] * srow[idx/9];
        sum += m*m;
    }
#pragma unroll
    for (int off = 16; off; off >>= 1)
        sum += __shfl_xor_sync(0xffffffffu, sum, off);
    if (lane == 0) {
        const float scale  = rsqrtf((float)RED);       // 1/sqrt(4608)
        const float scale2 = 1.0f/(float)RED;
        g_D[gw] = scale * rsqrtf(scale2*sum + 1e-8f);
    }
}

// ---------------------------------------------------------------------------
// K4: main conv. Block tile: 64 couts x (8 rows x 32 cols) pixels.
//     Thread (tm in [0,8), tn in [0,32)) owns 8 couts x 8 pixel-rows.
//     cin chunk = 8. x-tile modulated by s at smem load.
// ---------------------------------------------------------------------------
#define TM 64
#define TH 8
#define TW 32
#define CC 8

__global__ void __launch_bounds__(256, 2)
k_conv(const float* __restrict__ x, float* __restrict__ out) {
    __shared__ __align__(16) float xs[CC][TH+2][TW+2];
    __shared__ __align__(16) float ws[CC*KAREA][TM];

    const int b   = blockIdx.z;
    const int co0 = blockIdx.y * TM;
    const int y0  = (blockIdx.x >> 1) * TH;
    const int x0  = (blockIdx.x & 1)  * TW;
    const int tid = threadIdx.x;
    const int tn  = tid & 31;
    const int tm  = tid >> 5;

    float acc[8][8];
#pragma unroll
    for (int mi = 0; mi < 8; mi++)
#pragma unroll
        for (int py = 0; py < 8; py++) acc[mi][py] = 0.f;

    const float* sb = g_S + b*CIN;
    const float* xb = x + (size_t)b*CIN*H*W;

    for (int cc = 0; cc < CIN; cc += CC) {
        __syncthreads();   // protect smem reuse across iterations

        // --- load x tile (with halo), modulated by s[b][ci] ---
        for (int idx = tid; idx < CC*(TH+2)*(TW+2); idx += 256) {
            int ci  = idx / ((TH+2)*(TW+2));
            int rem = idx % ((TH+2)*(TW+2));
            int yy  = rem / (TW+2);
            int xx  = rem % (TW+2);
            int gy  = y0 + yy - 1;
            int gx  = x0 + xx - 1;
            float v = 0.f;
            if (gy >= 0 && gy < H && gx >= 0 && gx < W)
                v = xb[((size_t)(cc+ci)*H + gy)*W + gx] * sb[cc+ci];
            xs[ci][yy][xx] = v;
        }

        // --- load weight tile: rows (ci,k) in chunk, 64 contiguous couts ---
        {
            const float4* wt4 = (const float4*)(g_wT + (size_t)cc*KAREA*COUT + co0);
            float4* ws4 = (float4*)ws;
            for (int idx = tid; idx < CC*KAREA*(TM/4); idx += 256) {
                int r = idx >> 4;      // 0..71
                int c = idx & 15;      // float4 within 64-cout row
                ws4[r*(TM/4) + c] = wt4[(size_t)r*(COUT/4) + c];
            }
        }
        __syncthreads();

        // --- compute ---
        for (int ci = 0; ci < CC; ci++) {
#pragma unroll
            for (int ky = 0; ky < 3; ky++) {
#pragma unroll
                for (int kx = 0; kx < 3; kx++) {
                    const int r = ci*KAREA + ky*3 + kx;
                    float4 wa = *(const float4*)&ws[r][tm*8];
                    float4 wb = *(const float4*)&ws[r][tm*8+4];
                    float w8[8] = {wa.x, wa.y, wa.z, wa.w,
                                   wb.x, wb.y, wb.z, wb.w};
                    float xv[8];
#pragma unroll
                    for (int py = 0; py < 8; py++)
                        xv[py] = xs[ci][py+ky][tn+kx];
#pragma unroll
                    for (int mi = 0; mi < 8; mi++)
#pragma unroll
                        for (int py = 0; py < 8; py++)
                            acc[mi][py] = fmaf(w8[mi], xv[py], acc[mi][py]);
                }
            }
        }
    }

    // --- epilogue: apply scale*demod, store ---
    float dv[8];
#pragma unroll
    for (int mi = 0; mi < 8; mi++)
        dv[mi] = g_D[b*COUT + co0 + tm*8 + mi];
#pragma unroll
    for (int mi = 0; mi < 8; mi++) {
        int o = co0 + tm*8 + mi;
        float* op = out + (((size_t)b*COUT + o)*H + y0)*W + x0 + tn;
#pragma unroll
        for (int py = 0; py < 8; py++)
            op[(size_t)py*W] = acc[mi][py] * dv[mi];
    }
}

// ---------------------------------------------------------------------------
extern "C" void kernel_launch(void* const* d_in, const int* in_sizes, int n_in,
                              void* d_out, int out_size) {
    // Identify inputs by element count (all distinct) — robust to ordering.
    const float *x = nullptr, *style = nullptr, *weight = nullptr, *mod_w = nullptr;
    for (int i = 0; i < n_in; i++) {
        switch (in_sizes[i]) {
            case B*CIN*H*W:        x      = (const float*)d_in[i]; break; // 16777216
            case B*CIN:            style  = (const float*)d_in[i]; break; // 4096
            case COUT*CIN*KAREA:   weight = (const float*)d_in[i]; break; // 2359296
            case CIN*CIN:          mod_w  = (const float*)d_in[i]; break; // 262144
        }
    }
    float* out = (float*)d_out;

    k_style<<<B, CIN>>>(style, mod_w);

    dim3 gt(RED/32, COUT/32);
    k_wt<<<gt, dim3(32,8)>>>(weight);

    k_demod<<<(B*COUT)/8, 256>>>(weight);

    dim3 gc((H/TH)*(W/TW), COUT/TM, B);
    k_conv<<<gc, 256>>>(x, out);
}

// round 4
// speedup vs baseline: 5.0836x; 5.0799x over previous
#include <cuda_runtime.h>
#include <cuda_fp16.h>
#include <cstdint>
#include <math.h>

#define Bsz   8
#define CIN   512
#define COUT  512
#define HH    64
#define WW    64
#define KAREA 9
#define RED   (CIN*KAREA)

#define BK      32
#define NCHUNK  (KAREA*(CIN/BK))   // 144
#define XPAD_H  66
#define XROW    64
#define XPLANE  (XPAD_H*XROW)      // 4224

// ---------------- static device scratch --------------------------------------
__device__ float  g_S[Bsz*CIN];
__device__ float  g_D[Bsz*COUT];
__device__ __half g_Ah[(size_t)KAREA*COUT*CIN];        // [sh][o][i]
__device__ __half g_Xh[(size_t)3*Bsz*CIN*XPLANE];      // [kx][b][ci][y+1][x], pads stay 0

// ---------------- helpers ------------------------------------------------------
__device__ __forceinline__ uint32_t smem_u32(const void* p){
    uint32_t a;
    asm("{ .reg .u64 t; cvta.to.shared.u64 t, %1; cvt.u32.u64 %0, t; }" : "=r"(a) : "l"(p));
    return a;
}
__device__ __forceinline__ void cp16(uint32_t dst, const void* src){
    asm volatile("cp.async.cg.shared.global [%0], [%1], 16;" :: "r"(dst), "l"(src));
}
__device__ __forceinline__ void ldsm_x4(uint32_t* r, uint32_t addr){
    asm volatile("ldmatrix.sync.aligned.m8n8.x4.shared.b16 {%0,%1,%2,%3}, [%4];"
                 : "=r"(r[0]),"=r"(r[1]),"=r"(r[2]),"=r"(r[3]) : "r"(addr));
}
__device__ __forceinline__ void ldsm_x4t(uint32_t* r, uint32_t addr){
    asm volatile("ldmatrix.sync.aligned.m8n8.x4.trans.shared.b16 {%0,%1,%2,%3}, [%4];"
                 : "=r"(r[0]),"=r"(r[1]),"=r"(r[2]),"=r"(r[3]) : "r"(addr));
}
__device__ __forceinline__ void mma_f16(float* c, const uint32_t* a, const uint32_t* b){
    asm volatile("mma.sync.aligned.m16n8k16.row.col.f32.f16.f16.f32 "
        "{%0,%1,%2,%3}, {%4,%5,%6,%7}, {%8,%9}, {%0,%1,%2,%3};"
        : "+f"(c[0]),"+f"(c[1]),"+f"(c[2]),"+f"(c[3])
        : "r"(a[0]),"r"(a[1]),"r"(a[2]),"r"(a[3]), "r"(b[0]),"r"(b[1]));
}

// ---------------- prep kernels ------------------------------------------------
__global__ void k_style(const float* __restrict__ style, const float* __restrict__ mw){
    __shared__ float st[CIN];
    int b = blockIdx.x;
    st[threadIdx.x] = style[b*CIN + threadIdx.x];
    __syncthreads();
    const float* row = mw + (size_t)threadIdx.x*CIN;
    float acc = 0.f;
#pragma unroll 8
    for (int j = 0; j < CIN; j++) acc += row[j]*st[j];
    g_S[b*CIN + threadIdx.x] = acc;
}

__global__ void k_demod(const float* __restrict__ w){
    int gw   = blockIdx.x*8 + (threadIdx.x >> 5);
    int lane = threadIdx.x & 31;
    int b = gw >> 9, o = gw & 511;
    const float* wr = w + (size_t)o*RED;
    const float* sr = g_S + b*CIN;
    float sum = 0.f;
    for (int idx = lane; idx < RED; idx += 32){
        float m = wr[idx]*sr[idx/9];
        sum += m*m;
    }
#pragma unroll
    for (int off = 16; off; off >>= 1) sum += __shfl_xor_sync(~0u, sum, off);
    if (!lane)
        g_D[gw] = rsqrtf((float)RED) * rsqrtf(sum/(float)RED + 1e-8f);
}

__global__ void k_packw(const float* __restrict__ w){
    int gid = blockIdx.x*256 + threadIdx.x;
    int i = gid & 511;
    int o = (gid >> 9) & 511;
    int k = gid >> 18;
    g_Ah[((size_t)k*COUT + o)*CIN + i] = __float2half_rn(w[((size_t)o*CIN + i)*KAREA + k]);
}

__global__ void k_prepx(const float* __restrict__ x){
    int gid = blockIdx.x*256 + threadIdx.x;
    int xc = gid & 63;
    int y  = (gid >> 6) & 63;
    int ci = (gid >> 12) & 511;
    int b  = gid >> 21;
    __half v = __float2half_rn(x[gid] * g_S[b*CIN + ci]);
    size_t planeBase = ((size_t)b*CIN + ci)*XPLANE + (size_t)(y+1)*XROW;
    const size_t kxStride = (size_t)Bsz*CIN*XPLANE;
#pragma unroll
    for (int kx = 0; kx < 3; kx++){
        int dx = xc + 1 - kx;
        if (dx >= 0 && dx < 64)
            g_Xh[(size_t)kx*kxStride + planeBase + dx] = v;
    }
}

// ---------------- main mma.sync kernel ------------------------------------------
// CTA: 128 couts x 128 px (2 image rows). 8 warps (2m x 4n), warp tile 64x32.
// K loop: 144 chunks of 32 (9 shifts x 16 cin chunks). Double-buffered cp.async.

#define APAD 40    // halfs per A row (80B)
#define BPAD 136   // halfs per B row (272B)

__global__ void __launch_bounds__(256)
k_conv_mma(float* __restrict__ out)
{
    __shared__ __align__(16) __half As[2][128][APAD];
    __shared__ __align__(16) __half Bs[2][BK][BPAD];

    const int tid  = threadIdx.x;
    const int lane = tid & 31;
    const int wid  = tid >> 5;
    const int wm   = wid >> 2;           // 0..1
    const int wn   = wid & 3;            // 0..3

    const int b   = blockIdx.z;
    const int co0 = blockIdx.y << 7;     // cout tile base
    const int y0  = blockIdx.x << 1;     // 2 image rows per tile

    const uint32_t sA0 = smem_u32(&As[0][0][0]);
    const uint32_t sB0 = smem_u32(&Bs[0][0][0]);
    const uint32_t A_BUF = 128*APAD*2;   // bytes per A stage
    const uint32_t B_BUF = BK*BPAD*2;    // bytes per B stage

    float acc[4][4][4];
#pragma unroll
    for (int mt = 0; mt < 4; mt++)
#pragma unroll
        for (int nt = 0; nt < 4; nt++)
#pragma unroll
            for (int r = 0; r < 4; r++) acc[mt][nt][r] = 0.f;

    // ---- chunk loader ----
    auto load_chunk = [&](int ch, int buf){
        int sh  = ch >> 4;
        int ci0 = (ch & 15) << 5;
        int ky  = sh / 3;
        int kx  = sh - ky*3;
        const __half* aSrc = g_Ah + ((size_t)sh*COUT + co0)*CIN + ci0;
        const __half* xSrc = g_Xh + (((size_t)kx*Bsz + b)*CIN + ci0)*XPLANE
                           + (size_t)(y0 + ky)*XROW;
        uint32_t dA = sA0 + buf*A_BUF;
        uint32_t dB = sB0 + buf*B_BUF;
#pragma unroll
        for (int it = 0; it < 4; it++){
            int idx = tid + (it << 8);
            if (idx < 512){                       // A: 128 rows x 64B
                int m = idx >> 2, q = idx & 3;
                cp16(dA + m*(APAD*2) + q*16, aSrc + (size_t)m*CIN + (q<<3));
            } else {                              // B: 32 rows x 256B (2 y-rows)
                int i2  = idx - 512;
                int k   = i2 >> 4;
                int rem = i2 & 15;
                int yoff = rem >> 3;
                int xo   = (rem & 7) << 3;
                cp16(dB + k*(BPAD*2) + rem*16,
                     xSrc + (size_t)k*XPLANE + (size_t)yoff*XROW + xo);
            }
        }
        asm volatile("cp.async.commit_group;");
    };

    load_chunk(0, 0);

    for (int c = 0; c < NCHUNK; c++){
        int s = c & 1;
        if (c + 1 < NCHUNK){
            load_chunk(c+1, s^1);
            asm volatile("cp.async.wait_group 1;");
        } else {
            asm volatile("cp.async.wait_group 0;");
        }
        __syncthreads();

        const uint32_t aBase = sA0 + s*A_BUF;
        const uint32_t bBase = sB0 + s*B_BUF;
#pragma unroll
        for (int ks = 0; ks < 2; ks++){
            uint32_t afr[4][4], bfr[2][4];
#pragma unroll
            for (int mt = 0; mt < 4; mt++){
                int row = wm*64 + mt*16 + (lane & 15);
                int col = ks*16 + ((lane >> 4) << 3);
                ldsm_x4(afr[mt], aBase + (row*APAD + col)*2);
            }
#pragma unroll
            for (int np = 0; np < 2; np++){
                int g  = lane >> 3;
                int lr = lane & 7;
                int row = ks*16 + ((g & 1) << 3) + lr;
                int col = wn*32 + np*16 + ((g >> 1) << 3);
                ldsm_x4t(bfr[np], bBase + (row*BPAD + col)*2);
            }
#pragma unroll
            for (int mt = 0; mt < 4; mt++)
#pragma unroll
                for (int nt = 0; nt < 4; nt++)
                    mma_f16(acc[mt][nt], afr[mt], &bfr[nt>>1][(nt&1)*2]);
        }
        __syncthreads();
    }

    // ---- epilogue: scale*demod, store ----
    const int row0 = lane >> 2;
    const int col0 = (lane & 3) << 1;
#pragma unroll
    for (int mt = 0; mt < 4; mt++){
        int cout_a = co0 + wm*64 + mt*16 + row0;
        int cout_b = cout_a + 8;
        float dva = g_D[b*COUT + cout_a];
        float dvb = g_D[b*COUT + cout_b];
        float* opa = out + ((size_t)(b*COUT + cout_a)*HH + y0)*WW;
        float* opb = out + ((size_t)(b*COUT + cout_b)*HH + y0)*WW;
#pragma unroll
        for (int nt = 0; nt < 4; nt++){
            int n = wn*32 + nt*8 + col0;   // 0..127
            int yy = n >> 6;
            int xx = n & 63;
            float2 va, vb;
            va.x = acc[mt][nt][0]*dva; va.y = acc[mt][nt][1]*dva;
            vb.x = acc[mt][nt][2]*dvb; vb.y = acc[mt][nt][3]*dvb;
            *(float2*)(opa + (size_t)yy*WW + xx) = va;
            *(float2*)(opb + (size_t)yy*WW + xx) = vb;
        }
    }
}

// ---------------- launch --------------------------------------------------------
extern "C" void kernel_launch(void* const* d_in, const int* in_sizes, int n_in,
                              void* d_out, int out_size) {
    const float *x = nullptr, *style = nullptr, *weight = nullptr, *mod_w = nullptr;
    for (int i = 0; i < n_in; i++){
        switch (in_sizes[i]){
            case Bsz*CIN*HH*WW:   x      = (const float*)d_in[i]; break;
            case Bsz*CIN:         style  = (const float*)d_in[i]; break;
            case COUT*CIN*KAREA:  weight = (const float*)d_in[i]; break;
            case CIN*CIN:         mod_w  = (const float*)d_in[i]; break;
        }
    }
    float* out = (float*)d_out;

    k_style<<<Bsz, CIN>>>(style, mod_w);
    k_demod<<<(Bsz*COUT)/8, 256>>>(weight);
    k_packw<<<(KAREA*COUT*CIN)/256, 256>>>(weight);
    k_prepx<<<(Bsz*CIN*HH*WW)/256, 256>>>(x);

    dim3 grid(HH/2, COUT/128, Bsz);      // 32 x 4 x 8 = 1024 CTAs
    k_conv_mma<<<grid, 256>>>(out);
}